// round 14
// baseline (speedup 1.0000x reference)
#include <cuda_runtime.h>
#include <cuda_bf16.h>
#include <math.h>

#define HS 65536
#define TOUT 63489
#define NLAYER 20
#define FTT 128

__device__ __nv_bfloat16 g_hh[2*64*HS + 8192];
__device__ __nv_bfloat16 g_hl[2*64*HS + 8192];
__device__ float g_hf[2ll*64*HS];           // fp32 h plane (for FFMA path)
__device__ float g_skip[64*TOUT];
__device__ float g_w1t[NLAYER*128*128];     // [l][k][m]
__device__ float g_w2t[NLAYER*64*128];

__device__ __forceinline__ unsigned bf2pack(__nv_bfloat16 a, __nv_bfloat16 b){
    return (unsigned)__bfloat16_as_ushort(a) | ((unsigned)__bfloat16_as_ushort(b)<<16);
}
__device__ __forceinline__ void split2(float a, float b, unsigned& h, unsigned& l){
    __nv_bfloat16 ha=__float2bfloat16(a), hb=__float2bfloat16(b);
    h = bf2pack(ha,hb);
    l = bf2pack(__float2bfloat16(a-__bfloat162float(ha)), __float2bfloat16(b-__bfloat162float(hb)));
}
__device__ __forceinline__ float blo(unsigned u){ return __bfloat162float(__ushort_as_bfloat16((unsigned short)(u&0xffff))); }
__device__ __forceinline__ float bhi(unsigned u){ return __bfloat162float(__ushort_as_bfloat16((unsigned short)(u>>16))); }
__device__ __forceinline__ void ldsm2t(unsigned a, unsigned* d){
    asm volatile("ldmatrix.sync.aligned.m8n8.x2.trans.shared.b16 {%0,%1},[%2];"
        :"=r"(d[0]),"=r"(d[1]):"r"(a));
}
__device__ __forceinline__ void mma_bf(float* d, const unsigned* a, const unsigned* b){
    asm volatile("mma.sync.aligned.m16n8k16.row.col.f32.bf16.bf16.f32 "
        "{%0,%1,%2,%3},{%4,%5,%6,%7},{%8,%9},{%0,%1,%2,%3};\n"
        :"+f"(d[0]),"+f"(d[1]),"+f"(d[2]),"+f"(d[3])
        :"r"(a[0]),"r"(a[1]),"r"(a[2]),"r"(a[3]),"r"(b[0]),"r"(b[1]));
}
__device__ __forceinline__ float exp2_fma(float y){
    float ft = y + 12582912.0f;
    int ii = __float_as_int(ft) - 0x4B400000;
    float f = y - (ft - 12582912.0f);
    float p = 1.3333558146e-3f;
    p = fmaf(p, f, 9.6181291794e-3f);
    p = fmaf(p, f, 5.5504108664e-2f);
    p = fmaf(p, f, 2.4022650695e-1f);
    p = fmaf(p, f, 6.9314718056e-1f);
    p = fmaf(p, f, 1.0f);
    return p * __int_as_float((ii + 127) << 23);
}
__device__ __forceinline__ float rcp_12(float d){
    float r = fmaf(-0.470588235f, d, 1.411764706f);
    r = r * fmaf(-d, r, 2.0f);
    r = r * fmaf(-d, r, 2.0f);
    return r;
}
__device__ __forceinline__ float fast_tanh(float x){
    float u = exp2_fma(fmaxf(fabsf(x) * -2.88539008f, -30.0f));
    return copysignf((1.0f - u) * rcp_12(1.0f + u), x);
}
__device__ __forceinline__ float fast_sig(float x){
    float u = exp2_fma(fmaxf(fabsf(x) * -1.44269504f, -30.0f));
    float r = rcp_12(1.0f + u);
    return (x >= 0.0f) ? r : u * r;
}

__global__ void init_kernel(const float* __restrict__ in, const float* __restrict__ w0,
                            const float* __restrict__ b0,
                            const float* __restrict__ wf, const float* __restrict__ wg,
                            const float* __restrict__ wr, const float* __restrict__ ws){
    int st = gridDim.x*blockDim.x;
    int t0 = blockIdx.x*blockDim.x+threadIdx.x;
    for (int i = t0; i < 64*HS; i += st){
        float v = w0[i>>16]*in[i&(HS-1)] + b0[i>>16];
        __nv_bfloat16 h = __float2bfloat16(v);
        g_hh[i] = h; g_hl[i] = __float2bfloat16(v-__bfloat162float(h));
        g_hf[i] = v;
    }
    for (int i = t0; i < 64*TOUT; i += st) g_skip[i] = 0.0f;
    for (int i = t0; i < NLAYER*128*128; i += st){
        int l=i>>14, r=i&16383, k=r>>7, m=r&127;
        int c=k&63, lr=k>>6;
        g_w1t[i] = (m<64)? wf[((l*64+m)*64+c)*2+lr] : wg[((l*64+(m-64))*64+c)*2+lr];
    }
    for (int i = t0; i < NLAYER*64*128; i += st){
        int l=i>>13, r=i&8191, k=r>>7, m=r&127;
        g_w2t[i] = (m<64)? wr[(l*64+m)*64+k] : ws[(l*64+(m-64))*64+k];
    }
}

// smem: XH[0,32K) XL[32K,64K) W1h[64K,96K) W1l[96K,128K) W2h[128K,144K) W2l[144K,160K)
#define SM_LAYER 163840
__global__ void __launch_bounds__(1024,1) layer_kernel(
    const float* __restrict__ wf, const float* __restrict__ wg,
    const float* __restrict__ wr, const float* __restrict__ ws,
    const float* __restrict__ bfp, const float* __restrict__ bgp,
    const float* __restrict__ brp, const float* __restrict__ bsp,
    const float* __restrict__ w1t, const float* __restrict__ w2t,
    int inbuf, int W, int d, int skip_shift)
{
    extern __shared__ unsigned char smem[];
    unsigned char* sXh = smem;
    unsigned char* sXl = smem + 32768;
    unsigned* sW1h = (unsigned*)(smem+65536);
    unsigned* sW1l = (unsigned*)(smem+98304);
    unsigned* sW2h = (unsigned*)(smem+131072);
    unsigned* sW2l = (unsigned*)(smem+147456);
    const int tid=threadIdx.x, lane=tid&31, warp=tid>>5;

    const __nv_bfloat16* hinh = g_hh + (size_t)inbuf*(64*HS);
    const __nv_bfloat16* hinl = g_hl + (size_t)inbuf*(64*HS);
    __nv_bfloat16* houth = g_hh + (size_t)(1-inbuf)*(64*HS);
    __nv_bfloat16* houtl = g_hl + (size_t)(1-inbuf)*(64*HS);
    const float* hinf = g_hf + (size_t)inbuf*(64*HS);
    float* houtf = g_hf + (size_t)(1-inbuf)*(64*HS);

    // stage weights (all 1024 threads)
    for (int idx=tid; idx<128*64; idx+=1024){
        int m=idx&127, k0=(idx>>7)*2;
        int c0=k0&63, l0=k0>>6, c1=(k0+1)&63, l1=(k0+1)>>6;
        float v0 = (m<64)? wf[(m*64+c0)*2+l0] : wg[((m-64)*64+c0)*2+l0];
        float v1 = (m<64)? wf[(m*64+c1)*2+l1] : wg[((m-64)*64+c1)*2+l1];
        int ml=m&15, kl=k0&15;
        int r = ((ml>>3)&1) | (((kl>>3)&1)<<1);
        int w = (((m>>4)*8 + (k0>>4))<<7) + ((ml&7)*4 + ((kl>>1)&3))*4 + r;
        unsigned h,l; split2(v0,v1,h,l); sW1h[w]=h; sW1l[w]=l;
    }
    for (int idx=tid; idx<128*32; idx+=1024){
        int m=idx&127, k0=(idx>>7)*2;
        float v0 = (m<64)? wr[m*64+k0]   : ws[(m-64)*64+k0];
        float v1 = (m<64)? wr[m*64+k0+1] : ws[(m-64)*64+k0+1];
        int ml=m&15, kl=k0&15;
        int r = ((ml>>3)&1) | (((kl>>3)&1)<<1);
        int w = (((m>>4)*4 + (k0>>4))<<7) + ((ml&7)*4 + ((kl>>1)&3))*4 + r;
        unsigned h,l; split2(v0,v1,h,l); sW2h[w]=h; sW2l[w]=l;
    }
    __syncthreads();

    const int Wout = W-d;
    const int ntiles = (Wout+255)>>8;
    const int sh=d&7, q=sh>>1, odd=sh&1;

    if (warp < 16){
        // ===== TENSOR half: cols [t0, t0+128), warp owns 8 =====
        const int tw = warp*8;
        const int mat1=(lane>>3)&1, r8=lane&7;
        const unsigned bofs = (unsigned)((mat1*8 + r8)*256 + ((warp ^ r8)<<4));
        const unsigned xh_s = (unsigned)__cvta_generic_to_shared(sXh);
        const unsigned xl_s = (unsigned)__cvta_generic_to_shared(sXl);

        for (int tile=blockIdx.x; tile<ntiles; tile+=gridDim.x){
            const int t0 = tile<<8;
            __syncwarp();
            #pragma unroll
            for (int it=0; it<2; it++){
                int c = lane + 32*it;
                size_t g = (size_t)c*HS + t0 + tw;
                int aL = c*256 + ((warp ^ (c&7))<<4);
                *(uint4*)(sXh+aL) = *(const uint4*)(hinh+g);
                *(uint4*)(sXl+aL) = *(const uint4*)(hinl+g);
                int aR = (64+c)*256 + ((warp ^ (c&7))<<4);
                if (sh==0){
                    size_t gr = g + d;
                    *(uint4*)(sXh+aR) = *(const uint4*)(hinh+gr);
                    *(uint4*)(sXl+aR) = *(const uint4*)(hinl+gr);
                } else {
                    size_t gr = g + (d - sh);
                    unsigned wh[8], wl[8], oh[4], ol[4];
                    *(uint4*)&wh[0]=*(const uint4*)(hinh+gr); *(uint4*)&wh[4]=*(const uint4*)(hinh+gr+8);
                    *(uint4*)&wl[0]=*(const uint4*)(hinl+gr); *(uint4*)&wl[4]=*(const uint4*)(hinl+gr+8);
                    #pragma unroll
                    for (int i=0;i<4;i++){
                        int s=i+q;
                        oh[i] = odd ? __byte_perm(wh[s],wh[s+1],0x5432) : wh[s];
                        ol[i] = odd ? __byte_perm(wl[s],wl[s+1],0x5432) : wl[s];
                    }
                    *(uint4*)(sXh+aR)=*(uint4*)&oh[0];
                    *(uint4*)(sXl+aR)=*(uint4*)&ol[0];
                }
            }
            __syncwarp();

            float acc[8][4];
            #pragma unroll
            for (int a=0;a<8;a++){ acc[a][0]=acc[a][1]=acc[a][2]=acc[a][3]=0.f; }
            #pragma unroll
            for (int kc=0;kc<8;kc++){
                unsigned bh[2], bl[2];
                ldsm2t(xh_s + bofs + kc*4096, bh);
                ldsm2t(xl_s + bofs + kc*4096, bl);
                #pragma unroll
                for (int mt=0;mt<8;mt++){
                    uint4 A = *(const uint4*)(sW1h + ((mt*8+kc)<<7) + (lane<<2));
                    uint4 B = *(const uint4*)(sW1l + ((mt*8+kc)<<7) + (lane<<2));
                    unsigned ah[4]={A.x,A.y,A.z,A.w}, al[4]={B.x,B.y,B.z,B.w};
                    mma_bf(acc[mt],ah,bh);
                    mma_bf(acc[mt],ah,bl);
                    mma_bf(acc[mt],al,bh);
                }
            }
            #pragma unroll
            for (int mt=0;mt<4;mt++)
                #pragma unroll
                for (int rp=0;rp<2;rp++){
                    int mr = mt*16 + (lane>>2) + rp*8;
                    float bfv=bfp[mr], bgv=bgp[mr];
                    float z0 = fast_tanh(acc[mt][rp*2+0]+bfv)*fast_sig(acc[mt+4][rp*2+0]+bgv);
                    float z1 = fast_tanh(acc[mt][rp*2+1]+bfv)*fast_sig(acc[mt+4][rp*2+1]+bgv);
                    unsigned zh,zl; split2(z0,z1,zh,zl);
                    int ad = mr*256 + ((warp ^ (mr&7))<<4) + ((lane&3)<<2);
                    *(unsigned*)(sXh+ad)=zh; *(unsigned*)(sXl+ad)=zl;
                }
            __syncwarp();

            float ac2[8][4];
            #pragma unroll
            for (int a=0;a<8;a++){ ac2[a][0]=ac2[a][1]=ac2[a][2]=ac2[a][3]=0.f; }
            #pragma unroll
            for (int kc=0;kc<4;kc++){
                unsigned bh[2], bl[2];
                ldsm2t(xh_s + bofs + kc*4096, bh);
                ldsm2t(xl_s + bofs + kc*4096, bl);
                #pragma unroll
                for (int mt=0;mt<8;mt++){
                    uint4 A = *(const uint4*)(sW2h + ((mt*4+kc)<<7) + (lane<<2));
                    uint4 B = *(const uint4*)(sW2l + ((mt*4+kc)<<7) + (lane<<2));
                    unsigned ah[4]={A.x,A.y,A.z,A.w}, al[4]={B.x,B.y,B.z,B.w};
                    mma_bf(ac2[mt],ah,bh);
                    mma_bf(ac2[mt],ah,bl);
                    mma_bf(ac2[mt],al,bh);
                }
            }

            #pragma unroll
            for (int mt=0;mt<4;mt++)
                #pragma unroll
                for (int rp=0;rp<2;rp++){
                    int mr = mt*16 + (lane>>2) + rp*8;
                    float bias = brp[mr];
                    int gt = t0 + tw + ((lane&3)<<1);
                    int ra = (64+mr)*256 + ((warp ^ (mr&7))<<4) + ((lane&3)<<2);
                    unsigned rh=*(unsigned*)(sXh+ra), rl=*(unsigned*)(sXl+ra);
                    float v0 = ac2[mt][rp*2+0] + bias + blo(rh) + blo(rl);
                    float v1 = ac2[mt][rp*2+1] + bias + bhi(rh) + bhi(rl);
                    size_t go = (size_t)mr*HS + gt;
                    if (gt+1 < Wout){
                        unsigned oh,ol; split2(v0,v1,oh,ol);
                        *(unsigned*)(houth+go)=oh; *(unsigned*)(houtl+go)=ol;
                        float2 f2; f2.x=v0; f2.y=v1;
                        *(float2*)(houtf+go)=f2;
                    } else if (gt < Wout){
                        __nv_bfloat16 h=__float2bfloat16(v0);
                        houth[go]=h; houtl[go]=__float2bfloat16(v0-__bfloat162float(h));
                        houtf[go]=v0;
                    }
                }
            #pragma unroll
            for (int mt=4;mt<8;mt++)
                #pragma unroll
                for (int rp=0;rp<2;rp++){
                    int sr = (mt-4)*16 + (lane>>2) + rp*8;
                    float bias = bsp[sr];
                    int gt = t0 + tw + ((lane&3)<<1);
                    #pragma unroll
                    for (int e=0;e<2;e++){
                        int gc = gt+e - skip_shift;
                        if (gt+e < Wout && gc >= 0 && gc < TOUT){
                            float* p = &g_skip[sr*TOUT+gc];
                            *p = *p + ac2[mt][rp*2+e] + bias;
                        }
                    }
                }
        }
    } else {
        // ===== FFMA half: cols [t0+128, t0+256), warp owns 8 (4 units x 2) =====
        const int fw = warp - 16;
        const int m0 = lane*4;       // this lane's 4 rows of M=128
        for (int tile=blockIdx.x; tile<ntiles; tile+=gridDim.x){
            const int T0 = (tile<<8) + 128 + fw*8;
            #pragma unroll
            for (int u=0; u<4; u++){
                const int T = T0 + u*2;
                if (T >= Wout) break;
                const bool v1ok = (T+1 < Wout);

                float acc[4][2];
                #pragma unroll
                for (int i=0;i<4;i++){ acc[i][0]=0.f; acc[i][1]=0.f; }
                #pragma unroll 4
                for (int k=0;k<128;k++){
                    int ck = k&63;
                    int off = (k>=64)? d : 0;
                    float4 a = *(const float4*)(w1t + k*128 + m0);
                    const float* bp = hinf + (size_t)ck*HS + T + off;
                    float b0v = bp[0], b1v = bp[1];
                    #pragma unroll
                    for (int i=0;i<4;i++){
                        acc[i][0] = fmaf(((const float*)&a)[i], b0v, acc[i][0]);
                        acc[i][1] = fmaf(((const float*)&a)[i], b1v, acc[i][1]);
                    }
                }
                // activations + z via shfl_xor(16)
                float z[4][2];
                #pragma unroll
                for (int i=0;i<4;i++){
                    int m = m0 + i;
                    #pragma unroll
                    for (int c2=0;c2<2;c2++){
                        float av = (lane<16)? fast_tanh(acc[i][c2]+bfp[m])
                                            : fast_sig(acc[i][c2]+bgp[m-64]);
                        float pv = __shfl_xor_sync(0xffffffffu, av, 16);
                        z[i][c2] = av * pv;        // f*g both sides
                    }
                }
                // GEMM2: K=64, z broadcast from lanes 0..15
                float ac2[4][2];
                #pragma unroll
                for (int i=0;i<4;i++){ ac2[i][0]=0.f; ac2[i][1]=0.f; }
                #pragma unroll
                for (int k4=0;k4<16;k4++){
                    #pragma unroll
                    for (int j=0;j<4;j++){
                        int k = k4*4+j;
                        float4 a = *(const float4*)(w2t + k*128 + m0);
                        float zk0 = __shfl_sync(0xffffffffu, z[j][0], k4);
                        float zk1 = __shfl_sync(0xffffffffu, z[j][1], k4);
                        #pragma unroll
                        for (int i=0;i<4;i++){
                            ac2[i][0] = fmaf(((const float*)&a)[i], zk0, ac2[i][0]);
                            ac2[i][1] = fmaf(((const float*)&a)[i], zk1, ac2[i][1]);
                        }
                    }
                }
                // epilogue
                if (lane < 16){
                    #pragma unroll
                    for (int i=0;i<4;i++){
                        int m = m0 + i;
                        float bias = brp[m];
                        #pragma unroll
                        for (int c2=0;c2<2;c2++){
                            int gt = T + c2;
                            if (c2==0 || v1ok){
                                float v = ac2[i][c2] + bias + hinf[(size_t)m*HS + gt + d];
                                size_t go = (size_t)m*HS + gt;
                                houtf[go] = v;
                                __nv_bfloat16 h=__float2bfloat16(v);
                                houth[go]=h; houtl[go]=__float2bfloat16(v-__bfloat162float(h));
                            }
                        }
                    }
                } else {
                    #pragma unroll
                    for (int i=0;i<4;i++){
                        int s = m0 - 64 + i;
                        float bias = bsp[s];
                        #pragma unroll
                        for (int c2=0;c2<2;c2++){
                            int gt = T + c2;
                            int gc = gt - skip_shift;
                            if ((c2==0 || v1ok) && gc >= 0 && gc < TOUT){
                                float* p = &g_skip[s*TOUT+gc];
                                *p = *p + ac2[i][c2] + bias;
                            }
                        }
                    }
                }
            }
        }
    }
}

// -------- output head (R12 verbatim) --------
__device__ __forceinline__ unsigned pack_hl(float x){
    __nv_bfloat16 h=__float2bfloat16(x);
    __nv_bfloat16 l=__float2bfloat16(x-__bfloat162float(h));
    return (unsigned)__bfloat16_as_ushort(h) | ((unsigned)__bfloat16_as_ushort(l)<<16);
}
__device__ __forceinline__ int addrA(int m,int k,int kt){
    int ln=((m&7)<<2)|((k>>1)&3);
    int w=(k&1)|(((m>>3)&1)<<1)|(((k>>3)&1)<<2);
    return ((((m>>4)*kt+(k>>4))<<8)+(ln<<3)+w);
}
__device__ __forceinline__ int addrB(int k,int t){
    int ln=((t&7)<<2)|((k>>1)&3);
    int w=(k&1)|(((k>>3)&1)<<1);
    return ((((k>>4)*(FTT>>3)+(t>>3))<<7)+(ln<<2)+w);
}
__device__ __forceinline__ void loadA(const unsigned* s,int mt,int kc,int kt,int lane,unsigned* Ah,unsigned* Al){
    const uint4* p=(const uint4*)(s+(((mt*kt+kc)<<8)+(lane<<3)));
    uint4 q0=p[0],q1=p[1];
    Ah[0]=__byte_perm(q0.x,q0.y,0x5410); Al[0]=__byte_perm(q0.x,q0.y,0x7632);
    Ah[1]=__byte_perm(q0.z,q0.w,0x5410); Al[1]=__byte_perm(q0.z,q0.w,0x7632);
    Ah[2]=__byte_perm(q1.x,q1.y,0x5410); Al[2]=__byte_perm(q1.x,q1.y,0x7632);
    Ah[3]=__byte_perm(q1.z,q1.w,0x5410); Al[3]=__byte_perm(q1.z,q1.w,0x7632);
}
__device__ __forceinline__ void loadB(const unsigned* s,int kc,int nt,int lane,unsigned* Bh,unsigned* Bl){
    uint4 q=*(const uint4*)(s+(((kc*(FTT>>3)+nt)<<7)+(lane<<2)));
    Bh[0]=__byte_perm(q.x,q.y,0x5410); Bl[0]=__byte_perm(q.x,q.y,0x7632);
    Bh[1]=__byte_perm(q.z,q.w,0x5410); Bl[1]=__byte_perm(q.z,q.w,0x7632);
}
__global__ void __launch_bounds__(512,1) final_kernel(
    const float* __restrict__ alpha,
    const float* __restrict__ w0p, const float* __restrict__ b0p,
    const float* __restrict__ w1p, const float* __restrict__ b1p,
    float* __restrict__ out)
{
    extern __shared__ unsigned fs[];
    unsigned* sW0=fs; unsigned* sW1=fs+4096; unsigned* sB0=fs+20480; unsigned* sB1=fs+28672;
    const int tid=threadIdx.x, lane=tid&31, wrp=tid>>5;
    const int wm=wrp>>2, n0=(wrp&3)*32;

    for (int i=tid;i<64*64;i+=512) sW0[addrA(i>>6,i&63,4)]=pack_hl(w0p[i]);
    for (int i=tid;i<256*64;i+=512) sW1[addrA(i>>6,i&63,4)]=pack_hl(w1p[i]);
    __syncthreads();

    const int nt_total=(TOUT+FTT-1)/FTT;
    for (int tile=blockIdx.x; tile<nt_total; tile+=gridDim.x){
        const int t0=tile*FTT;
        for (int i=tid;i<64*FTT;i+=512){
            int c=i>>7, t=i&(FTT-1), gt=t0+t;
            float v=(gt<TOUT)?g_skip[c*TOUT+gt]:0.0f;
            v=(v>0.f)?v:alpha[c]*v;
            sB0[addrB(c,t)]=pack_hl(v);
        }
        __syncthreads();

        float a0[4][4];
        #pragma unroll
        for (int b=0;b<4;b++){ a0[b][0]=a0[b][1]=a0[b][2]=a0[b][3]=0.f; }
        #pragma unroll
        for (int kc=0;kc<4;kc++){
            unsigned Ah[4],Al[4],Bh[4][2],Bl[4][2];
            loadA(sW0,wm,kc,4,lane,Ah,Al);
            #pragma unroll
            for (int nt=0;nt<4;nt++) loadB(sB0,kc,(n0>>3)+nt,lane,Bh[nt],Bl[nt]);
            #pragma unroll
            for (int nt=0;nt<4;nt++){
                mma_bf(a0[nt],Ah,Bh[nt]); mma_bf(a0[nt],Ah,Bl[nt]); mma_bf(a0[nt],Al,Bh[nt]);
            }
        }
        #pragma unroll
        for (int nt=0;nt<4;nt++){
            int tb=n0+nt*8+((lane&3)<<1);
            #pragma unroll
            for (int r=0;r<4;r++){
                int m=wm*16+(lane>>2)+((r&2)?8:0);
                float v=a0[nt][r]+b0p[m];
                v=(v>0.f)?v:alpha[64+m]*v;
                sB1[addrB(m,tb+(r&1))]=pack_hl(v);
            }
        }
        __syncthreads();

        float a1[4][4][4];
        #pragma unroll
        for (int a=0;a<4;a++)
            #pragma unroll
            for (int b=0;b<4;b++){ a1[a][b][0]=a1[a][b][1]=a1[a][b][2]=a1[a][b][3]=0.f; }
        #pragma unroll
        for (int kc=0;kc<4;kc++){
            unsigned Ah[4][4],Al[4][4],Bh[4][2],Bl[4][2];
            #pragma unroll
            for (int mt=0;mt<4;mt++) loadA(sW1,wm*4+mt,kc,4,lane,Ah[mt],Al[mt]);
            #pragma unroll
            for (int nt=0;nt<4;nt++) loadB(sB1,kc,(n0>>3)+nt,lane,Bh[nt],Bl[nt]);
            #pragma unroll
            for (int mt=0;mt<4;mt++)
                #pragma unroll
                for (int nt=0;nt<4;nt++){
                    mma_bf(a1[mt][nt],Ah[mt],Bh[nt]); mma_bf(a1[mt][nt],Ah[mt],Bl[nt]); mma_bf(a1[mt][nt],Al[mt],Bh[nt]);
                }
        }
        #pragma unroll
        for (int mt=0;mt<4;mt++){
            int mb=wm*64+mt*16+(lane>>2);
            #pragma unroll
            for (int nt=0;nt<4;nt++){
                int tb=n0+nt*8+((lane&3)<<1);
                #pragma unroll
                for (int r=0;r<4;r++){
                    int m=mb+((r&2)?8:0), gt=t0+tb+(r&1);
                    if (gt<TOUT) out[m*TOUT+gt]=a1[mt][nt][r]+b1p[m];
                }
            }
        }
        __syncthreads();
    }
}

extern "C" void kernel_launch(void* const* d_in, const int* in_sizes, int n_in,
                              void* d_out, int out_size) {
    const float* input =(const float*)d_in[0];
    const float* w0    =(const float*)d_in[1];
    const float* b0    =(const float*)d_in[2];
    const float* wf    =(const float*)d_in[3];
    const float* bf    =(const float*)d_in[4];
    const float* wg    =(const float*)d_in[5];
    const float* bg    =(const float*)d_in[6];
    const float* wr    =(const float*)d_in[7];
    const float* br    =(const float*)d_in[8];
    const float* ws    =(const float*)d_in[9];
    const float* bs    =(const float*)d_in[10];
    const float* alpha =(const float*)d_in[11];
    const float* w_out0=(const float*)d_in[12];
    const float* b_out0=(const float*)d_in[13];
    const float* w_out1=(const float*)d_in[14];
    const float* b_out1=(const float*)d_in[15];

    const int SMEM_FINAL = 36864*4;
    cudaFuncSetAttribute(layer_kernel, cudaFuncAttributeMaxDynamicSharedMemorySize, SM_LAYER);
    cudaFuncSetAttribute(final_kernel, cudaFuncAttributeMaxDynamicSharedMemorySize, SMEM_FINAL);

    init_kernel<<<512,256>>>(input, w0, b0, wf, wg, wr, ws);

    float* w1t_base = nullptr; float* w2t_base = nullptr;
    cudaGetSymbolAddress((void**)&w1t_base, g_w1t);
    cudaGetSymbolAddress((void**)&w2t_base, g_w2t);

    int W = HS, offset = 2048, buf = 0;
    for (int i = 0; i < NLAYER; i++){
        int d = 1 << (i % 10);
        offset -= d;
        layer_kernel<<<148,1024,SM_LAYER>>>(
            wf + i*64*64*2, wg + i*64*64*2, wr + i*64*64, ws + i*64*64,
            bf + i*64, bg + i*64, br + i*64, bs + i*64,
            w1t_base + i*128*128, w2t_base + i*64*128,
            buf, W, d, offset - 1);
        W -= d; buf ^= 1;
    }
    final_kernel<<<148,512,SMEM_FINAL>>>(alpha, w_out0, b_out0, w_out1, b_out1, (float*)d_out);
}

// round 15
// speedup vs baseline: 1.0803x; 1.0803x over previous
#include <cuda_runtime.h>
#include <cuda_bf16.h>
#include <math.h>

#define HS 65536
#define TOUT 63489
#define NLAYER 20
#define FTT 128

__device__ __nv_bfloat16 g_hh[2*64*HS + 8192];
__device__ __nv_bfloat16 g_hl[2*64*HS + 8192];
__device__ float g_skip[64*TOUT];
__device__ float g_w1t[NLAYER*128*128];   // [l][k][m]
__device__ float g_w2t[NLAYER*64*128];

__device__ __forceinline__ unsigned bf2pack(__nv_bfloat16 a, __nv_bfloat16 b){
    return (unsigned)__bfloat16_as_ushort(a) | ((unsigned)__bfloat16_as_ushort(b)<<16);
}
__device__ __forceinline__ void split2(float a, float b, unsigned& h, unsigned& l){
    __nv_bfloat16 ha=__float2bfloat16(a), hb=__float2bfloat16(b);
    h = bf2pack(ha,hb);
    l = bf2pack(__float2bfloat16(a-__bfloat162float(ha)), __float2bfloat16(b-__bfloat162float(hb)));
}
__device__ __forceinline__ float blo(unsigned u){ return __bfloat162float(__ushort_as_bfloat16((unsigned short)(u&0xffff))); }
__device__ __forceinline__ float bhi(unsigned u){ return __bfloat162float(__ushort_as_bfloat16((unsigned short)(u>>16))); }
__device__ __forceinline__ void ldsm2t(unsigned a, unsigned* d){
    asm volatile("ldmatrix.sync.aligned.m8n8.x2.trans.shared.b16 {%0,%1},[%2];"
        :"=r"(d[0]),"=r"(d[1]):"r"(a));
}
__device__ __forceinline__ void mma_bf(float* d, const unsigned* a, const unsigned* b){
    asm volatile("mma.sync.aligned.m16n8k16.row.col.f32.bf16.bf16.f32 "
        "{%0,%1,%2,%3},{%4,%5,%6,%7},{%8,%9},{%0,%1,%2,%3};\n"
        :"+f"(d[0]),"+f"(d[1]),"+f"(d[2]),"+f"(d[3])
        :"r"(a[0]),"r"(a[1]),"r"(a[2]),"r"(a[3]),"r"(b[0]),"r"(b[1]));
}
__device__ __forceinline__ float exp2_fma(float y){
    float ft = y + 12582912.0f;
    int ii = __float_as_int(ft) - 0x4B400000;
    float f = y - (ft - 12582912.0f);
    float p = 1.3333558146e-3f;
    p = fmaf(p, f, 9.6181291794e-3f);
    p = fmaf(p, f, 5.5504108664e-2f);
    p = fmaf(p, f, 2.4022650695e-1f);
    p = fmaf(p, f, 6.9314718056e-1f);
    p = fmaf(p, f, 1.0f);
    return p * __int_as_float((ii + 127) << 23);
}
__device__ __forceinline__ float rcp_12(float d){
    float r = fmaf(-0.470588235f, d, 1.411764706f);
    r = r * fmaf(-d, r, 2.0f);
    r = r * fmaf(-d, r, 2.0f);
    return r;
}
__device__ __forceinline__ float fast_tanh(float x){
    float u = exp2_fma(fmaxf(fabsf(x) * -2.88539008f, -30.0f));
    return copysignf((1.0f - u) * rcp_12(1.0f + u), x);
}
__device__ __forceinline__ float fast_sig(float x){
    float u = exp2_fma(fmaxf(fabsf(x) * -1.44269504f, -30.0f));
    float r = rcp_12(1.0f + u);
    return (x >= 0.0f) ? r : u * r;
}
__device__ __forceinline__ float hv(const __nv_bfloat16* hh, const __nv_bfloat16* hl, size_t i){
    return __bfloat162float(hh[i]) + __bfloat162float(hl[i]);
}

__global__ void init_kernel(const float* __restrict__ in, const float* __restrict__ w0,
                            const float* __restrict__ b0,
                            const float* __restrict__ wf, const float* __restrict__ wg,
                            const float* __restrict__ wr, const float* __restrict__ ws){
    int st = gridDim.x*blockDim.x;
    int t0 = blockIdx.x*blockDim.x+threadIdx.x;
    for (int i = t0; i < 64*HS; i += st){
        float v = w0[i>>16]*in[i&(HS-1)] + b0[i>>16];
        __nv_bfloat16 h = __float2bfloat16(v);
        g_hh[i] = h; g_hl[i] = __float2bfloat16(v-__bfloat162float(h));
    }
    for (int i = t0; i < 64*TOUT; i += st) g_skip[i] = 0.0f;
    for (int i = t0; i < NLAYER*128*128; i += st){
        int l=i>>14, r=i&16383, k=r>>7, m=r&127;
        int c=k&63, lr=k>>6;
        g_w1t[i] = (m<64)? wf[((l*64+m)*64+c)*2+lr] : wg[((l*64+(m-64))*64+c)*2+lr];
    }
    for (int i = t0; i < NLAYER*64*128; i += st){
        int l=i>>13, r=i&8191, k=r>>7, m=r&127;
        g_w2t[i] = (m<64)? wr[(l*64+m)*64+k] : ws[(l*64+(m-64))*64+k];
    }
}

// smem: sXh[0,32K) sXl[32K,64K) W1h[64K,96K) W1l[96K,128K) W2h[128K,144K) W2l[144K,160K) fX[160K,224K)
#define SM_LAYER 229376
__global__ void __launch_bounds__(1024,1) layer_kernel(
    const float* __restrict__ wf, const float* __restrict__ wg,
    const float* __restrict__ wr, const float* __restrict__ ws,
    const float* __restrict__ bfp, const float* __restrict__ bgp,
    const float* __restrict__ brp, const float* __restrict__ bsp,
    const float* __restrict__ w1t, const float* __restrict__ w2t,
    int inbuf, int W, int d, int skip_shift)
{
    extern __shared__ unsigned char smem[];
    unsigned char* sXh = smem;
    unsigned char* sXl = smem + 32768;
    unsigned* sW1h = (unsigned*)(smem+65536);
    unsigned* sW1l = (unsigned*)(smem+98304);
    unsigned* sW2h = (unsigned*)(smem+131072);
    unsigned* sW2l = (unsigned*)(smem+147456);
    const int tid=threadIdx.x, lane=tid&31, warp=tid>>5;

    const __nv_bfloat16* hinh = g_hh + (size_t)inbuf*(64*HS);
    const __nv_bfloat16* hinl = g_hl + (size_t)inbuf*(64*HS);
    __nv_bfloat16* houth = g_hh + (size_t)(1-inbuf)*(64*HS);
    __nv_bfloat16* houtl = g_hl + (size_t)(1-inbuf)*(64*HS);

    for (int idx=tid; idx<128*64; idx+=1024){
        int m=idx&127, k0=(idx>>7)*2;
        int c0=k0&63, l0=k0>>6, c1=(k0+1)&63, l1=(k0+1)>>6;
        float v0 = (m<64)? wf[(m*64+c0)*2+l0] : wg[((m-64)*64+c0)*2+l0];
        float v1 = (m<64)? wf[(m*64+c1)*2+l1] : wg[((m-64)*64+c1)*2+l1];
        int ml=m&15, kl=k0&15;
        int r = ((ml>>3)&1) | (((kl>>3)&1)<<1);
        int w = (((m>>4)*8 + (k0>>4))<<7) + ((ml&7)*4 + ((kl>>1)&3))*4 + r;
        unsigned h,l; split2(v0,v1,h,l); sW1h[w]=h; sW1l[w]=l;
    }
    for (int idx=tid; idx<128*32; idx+=1024){
        int m=idx&127, k0=(idx>>7)*2;
        float v0 = (m<64)? wr[m*64+k0]   : ws[(m-64)*64+k0];
        float v1 = (m<64)? wr[m*64+k0+1] : ws[(m-64)*64+k0+1];
        int ml=m&15, kl=k0&15;
        int r = ((ml>>3)&1) | (((kl>>3)&1)<<1);
        int w = (((m>>4)*4 + (k0>>4))<<7) + ((ml&7)*4 + ((kl>>1)&3))*4 + r;
        unsigned h,l; split2(v0,v1,h,l); sW2h[w]=h; sW2l[w]=l;
    }
    __syncthreads();

    const int Wout = W-d;
    const int ntiles = (Wout+255)>>8;
    const int sh=d&7, q=sh>>1, odd=sh&1;

    if (warp < 16){
        // ===== TENSOR half: cols [t0, t0+128), warp owns 8 (R13 machinery) =====
        const int tw = warp*8;
        const int mat1=(lane>>3)&1, r8=lane&7;
        const unsigned bofs = (unsigned)((mat1*8 + r8)*256 + ((warp ^ r8)<<4));
        const unsigned xh_s = (unsigned)__cvta_generic_to_shared(sXh);
        const unsigned xl_s = (unsigned)__cvta_generic_to_shared(sXl);

        for (int tile=blockIdx.x; tile<ntiles; tile+=gridDim.x){
            const int t0 = tile<<8;
            __syncwarp();
            #pragma unroll
            for (int it=0; it<2; it++){
                int c = lane + 32*it;
                size_t g = (size_t)c*HS + t0 + tw;
                int aL = c*256 + ((warp ^ (c&7))<<4);
                *(uint4*)(sXh+aL) = *(const uint4*)(hinh+g);
                *(uint4*)(sXl+aL) = *(const uint4*)(hinl+g);
                int aR = (64+c)*256 + ((warp ^ (c&7))<<4);
                if (sh==0){
                    size_t gr = g + d;
                    *(uint4*)(sXh+aR) = *(const uint4*)(hinh+gr);
                    *(uint4*)(sXl+aR) = *(const uint4*)(hinl+gr);
                } else {
                    size_t gr = g + (d - sh);
                    unsigned wh[8], wl[8], oh[4], ol[4];
                    *(uint4*)&wh[0]=*(const uint4*)(hinh+gr); *(uint4*)&wh[4]=*(const uint4*)(hinh+gr+8);
                    *(uint4*)&wl[0]=*(const uint4*)(hinl+gr); *(uint4*)&wl[4]=*(const uint4*)(hinl+gr+8);
                    #pragma unroll
                    for (int i=0;i<4;i++){
                        int s=i+q;
                        oh[i] = odd ? __byte_perm(wh[s],wh[s+1],0x5432) : wh[s];
                        ol[i] = odd ? __byte_perm(wl[s],wl[s+1],0x5432) : wl[s];
                    }
                    *(uint4*)(sXh+aR)=*(uint4*)&oh[0];
                    *(uint4*)(sXl+aR)=*(uint4*)&ol[0];
                }
            }
            __syncwarp();

            float acc[8][4];
            #pragma unroll
            for (int a=0;a<8;a++){ acc[a][0]=acc[a][1]=acc[a][2]=acc[a][3]=0.f; }
            #pragma unroll
            for (int kc=0;kc<8;kc++){
                unsigned bh[2], bl[2];
                ldsm2t(xh_s + bofs + kc*4096, bh);
                ldsm2t(xl_s + bofs + kc*4096, bl);
                #pragma unroll
                for (int mt=0;mt<8;mt++){
                    uint4 A = *(const uint4*)(sW1h + ((mt*8+kc)<<7) + (lane<<2));
                    uint4 B = *(const uint4*)(sW1l + ((mt*8+kc)<<7) + (lane<<2));
                    unsigned ah[4]={A.x,A.y,A.z,A.w}, al[4]={B.x,B.y,B.z,B.w};
                    mma_bf(acc[mt],ah,bh);
                    mma_bf(acc[mt],ah,bl);
                    mma_bf(acc[mt],al,bh);
                }
            }
            #pragma unroll
            for (int mt=0;mt<4;mt++)
                #pragma unroll
                for (int rp=0;rp<2;rp++){
                    int mr = mt*16 + (lane>>2) + rp*8;
                    float z0 = fast_tanh(acc[mt][rp*2+0]+bfp[mr])*fast_sig(acc[mt+4][rp*2+0]+bgp[mr]);
                    float z1 = fast_tanh(acc[mt][rp*2+1]+bfp[mr])*fast_sig(acc[mt+4][rp*2+1]+bgp[mr]);
                    unsigned zh,zl; split2(z0,z1,zh,zl);
                    int ad = mr*256 + ((warp ^ (mr&7))<<4) + ((lane&3)<<2);
                    *(unsigned*)(sXh+ad)=zh; *(unsigned*)(sXl+ad)=zl;
                }
            __syncwarp();

            float ac2[8][4];
            #pragma unroll
            for (int a=0;a<8;a++){ ac2[a][0]=ac2[a][1]=ac2[a][2]=ac2[a][3]=0.f; }
            #pragma unroll
            for (int kc=0;kc<4;kc++){
                unsigned bh[2], bl[2];
                ldsm2t(xh_s + bofs + kc*4096, bh);
                ldsm2t(xl_s + bofs + kc*4096, bl);
                #pragma unroll
                for (int mt=0;mt<8;mt++){
                    uint4 A = *(const uint4*)(sW2h + ((mt*4+kc)<<7) + (lane<<2));
                    uint4 B = *(const uint4*)(sW2l + ((mt*4+kc)<<7) + (lane<<2));
                    unsigned ah[4]={A.x,A.y,A.z,A.w}, al[4]={B.x,B.y,B.z,B.w};
                    mma_bf(ac2[mt],ah,bh);
                    mma_bf(ac2[mt],ah,bl);
                    mma_bf(ac2[mt],al,bh);
                }
            }

            #pragma unroll
            for (int mt=0;mt<4;mt++)
                #pragma unroll
                for (int rp=0;rp<2;rp++){
                    int mr = mt*16 + (lane>>2) + rp*8;
                    float bias = brp[mr];
                    int gt = t0 + tw + ((lane&3)<<1);
                    int ra = (64+mr)*256 + ((warp ^ (mr&7))<<4) + ((lane&3)<<2);
                    unsigned rh=*(unsigned*)(sXh+ra), rl=*(unsigned*)(sXl+ra);
                    float v0 = ac2[mt][rp*2+0] + bias + blo(rh) + blo(rl);
                    float v1 = ac2[mt][rp*2+1] + bias + bhi(rh) + bhi(rl);
                    size_t go = (size_t)mr*HS + gt;
                    if (gt+1 < Wout){
                        unsigned oh,ol; split2(v0,v1,oh,ol);
                        *(unsigned*)(houth+go)=oh; *(unsigned*)(houtl+go)=ol;
                    } else if (gt < Wout){
                        __nv_bfloat16 h=__float2bfloat16(v0);
                        houth[go]=h; houtl[go]=__float2bfloat16(v0-__bfloat162float(h));
                    }
                }
            #pragma unroll
            for (int mt=4;mt<8;mt++)
                #pragma unroll
                for (int rp=0;rp<2;rp++){
                    int sr = (mt-4)*16 + (lane>>2) + rp*8;
                    float bias = bsp[sr];
                    int gt = t0 + tw + ((lane&3)<<1);
                    #pragma unroll
                    for (int e=0;e<2;e++){
                        int gc = gt+e - skip_shift;
                        if (gt+e < Wout && gc >= 0 && gc < TOUT){
                            float* p = &g_skip[sr*TOUT+gc];
                            *p = *p + ac2[mt][rp*2+e] + bias;
                        }
                    }
                }
        }
    } else {
        // ===== FFMA half: cols [t0+128, t0+256), warp owns 8, smem fX slice =====
        const int fw = warp - 16;
        float* fXw = (float*)(smem + 163840) + fw*1024;   // 128 rows x 8 floats
        const int m0 = lane*4;
        for (int tile=blockIdx.x; tile<ntiles; tile+=gridDim.x){
            const int T0 = (tile<<8) + 128 + fw*8;
            __syncwarp();
            // stage B: rows {lane, lane+32, lane+64, lane+96}
            #pragma unroll
            for (int j=0;j<4;j++){
                int k = j*32 + lane;
                int c64 = k & 63;
                int off = (k>=64)? d : 0;
                size_t gb = (size_t)c64*HS + T0 + off;
                float v[8];
                #pragma unroll
                for (int c=0;c<8;c++) v[c] = hv(hinh, hinl, gb+c);
                *(float4*)(fXw + k*8)     = *(float4*)&v[0];
                *(float4*)(fXw + k*8 + 4) = *(float4*)&v[4];
            }
            __syncwarp();

            // GEMM1: M=128 (lane: 4 rows), N=8, K=128
            float acc[4][8];
            #pragma unroll
            for (int i=0;i<4;i++)
                #pragma unroll
                for (int c=0;c<8;c++) acc[i][c]=0.f;
            #pragma unroll 4
            for (int k=0;k<128;k++){
                float4 a = *(const float4*)(w1t + k*128 + m0);
                float4 b0 = *(const float4*)(fXw + k*8);
                float4 b1 = *(const float4*)(fXw + k*8 + 4);
                const float* bb0=(const float*)&b0;
                const float* bb1=(const float*)&b1;
                #pragma unroll
                for (int i=0;i<4;i++){
                    float av = ((const float*)&a)[i];
                    #pragma unroll
                    for (int c=0;c<4;c++){
                        acc[i][c]   = fmaf(av, bb0[c], acc[i][c]);
                        acc[i][c+4] = fmaf(av, bb1[c], acc[i][c+4]);
                    }
                }
            }
            // activations + z (pair lane <-> lane+16)
            #pragma unroll
            for (int i=0;i<4;i++){
                int m = m0+i;
                float bias = (lane<16)? bfp[m] : bgp[m-64];
                float zz[8];
                #pragma unroll
                for (int c=0;c<8;c++){
                    float av = (lane<16)? fast_tanh(acc[i][c]+bias) : fast_sig(acc[i][c]+bias);
                    float pv = __shfl_xor_sync(0xffffffffu, av, 16);
                    zz[c] = av*pv;
                }
                if (lane < 16){
                    *(float4*)(fXw + m*8)     = *(float4*)&zz[0];
                    *(float4*)(fXw + m*8 + 4) = *(float4*)&zz[4];
                }
            }
            __syncwarp();

            // GEMM2: K=64 (z rows 0..63)
            float ac2[4][8];
            #pragma unroll
            for (int i=0;i<4;i++)
                #pragma unroll
                for (int c=0;c<8;c++) ac2[i][c]=0.f;
            #pragma unroll 4
            for (int k=0;k<64;k++){
                float4 a = *(const float4*)(w2t + k*128 + m0);
                float4 b0 = *(const float4*)(fXw + k*8);
                float4 b1 = *(const float4*)(fXw + k*8 + 4);
                const float* bb0=(const float*)&b0;
                const float* bb1=(const float*)&b1;
                #pragma unroll
                for (int i=0;i<4;i++){
                    float av = ((const float*)&a)[i];
                    #pragma unroll
                    for (int c=0;c<4;c++){
                        ac2[i][c]   = fmaf(av, bb0[c], ac2[i][c]);
                        ac2[i][c+4] = fmaf(av, bb1[c], ac2[i][c+4]);
                    }
                }
            }
            // epilogue
            if (lane < 16){
                #pragma unroll
                for (int i=0;i<4;i++){
                    int m = m0+i;
                    float bias = brp[m];
                    #pragma unroll
                    for (int c=0;c<8;c++){
                        int gt = T0 + c;
                        if (gt < Wout){
                            float rv = hv(hinh, hinl, (size_t)m*HS + gt + d);
                            float v = ac2[i][c] + bias + rv;
                            size_t go = (size_t)m*HS + gt;
                            __nv_bfloat16 h=__float2bfloat16(v);
                            houth[go]=h; houtl[go]=__float2bfloat16(v-__bfloat162float(h));
                        }
                    }
                }
            } else {
                #pragma unroll
                for (int i=0;i<4;i++){
                    int s = m0-64+i;
                    float bias = bsp[s];
                    #pragma unroll
                    for (int c=0;c<8;c++){
                        int gt = T0 + c;
                        int gc = gt - skip_shift;
                        if (gt < Wout && gc >= 0 && gc < TOUT){
                            float* p = &g_skip[s*TOUT+gc];
                            *p = *p + ac2[i][c] + bias;
                        }
                    }
                }
            }
        }
    }
}

// -------- output head (R12 verbatim) --------
__device__ __forceinline__ unsigned pack_hl(float x){
    __nv_bfloat16 h=__float2bfloat16(x);
    __nv_bfloat16 l=__float2bfloat16(x-__bfloat162float(h));
    return (unsigned)__bfloat16_as_ushort(h) | ((unsigned)__bfloat16_as_ushort(l)<<16);
}
__device__ __forceinline__ int addrA(int m,int k,int kt){
    int ln=((m&7)<<2)|((k>>1)&3);
    int w=(k&1)|(((m>>3)&1)<<1)|(((k>>3)&1)<<2);
    return ((((m>>4)*kt+(k>>4))<<8)+(ln<<3)+w);
}
__device__ __forceinline__ int addrB(int k,int t){
    int ln=((t&7)<<2)|((k>>1)&3);
    int w=(k&1)|(((k>>3)&1)<<1);
    return ((((k>>4)*(FTT>>3)+(t>>3))<<7)+(ln<<2)+w);
}
__device__ __forceinline__ void loadA(const unsigned* s,int mt,int kc,int kt,int lane,unsigned* Ah,unsigned* Al){
    const uint4* p=(const uint4*)(s+(((mt*kt+kc)<<8)+(lane<<3)));
    uint4 q0=p[0],q1=p[1];
    Ah[0]=__byte_perm(q0.x,q0.y,0x5410); Al[0]=__byte_perm(q0.x,q0.y,0x7632);
    Ah[1]=__byte_perm(q0.z,q0.w,0x5410); Al[1]=__byte_perm(q0.z,q0.w,0x7632);
    Ah[2]=__byte_perm(q1.x,q1.y,0x5410); Al[2]=__byte_perm(q1.x,q1.y,0x7632);
    Ah[3]=__byte_perm(q1.z,q1.w,0x5410); Al[3]=__byte_perm(q1.z,q1.w,0x7632);
}
__device__ __forceinline__ void loadB(const unsigned* s,int kc,int nt,int lane,unsigned* Bh,unsigned* Bl){
    uint4 q=*(const uint4*)(s+(((kc*(FTT>>3)+nt)<<7)+(lane<<2)));
    Bh[0]=__byte_perm(q.x,q.y,0x5410); Bl[0]=__byte_perm(q.x,q.y,0x7632);
    Bh[1]=__byte_perm(q.z,q.w,0x5410); Bl[1]=__byte_perm(q.z,q.w,0x7632);
}
__global__ void __launch_bounds__(512,1) final_kernel(
    const float* __restrict__ alpha,
    const float* __restrict__ w0p, const float* __restrict__ b0p,
    const float* __restrict__ w1p, const float* __restrict__ b1p,
    float* __restrict__ out)
{
    extern __shared__ unsigned fs[];
    unsigned* sW0=fs; unsigned* sW1=fs+4096; unsigned* sB0=fs+20480; unsigned* sB1=fs+28672;
    const int tid=threadIdx.x, lane=tid&31, wrp=tid>>5;
    const int wm=wrp>>2, n0=(wrp&3)*32;

    for (int i=tid;i<64*64;i+=512) sW0[addrA(i>>6,i&63,4)]=pack_hl(w0p[i]);
    for (int i=tid;i<256*64;i+=512) sW1[addrA(i>>6,i&63,4)]=pack_hl(w1p[i]);
    __syncthreads();

    const int nt_total=(TOUT+FTT-1)/FTT;
    for (int tile=blockIdx.x; tile<nt_total; tile+=gridDim.x){
        const int t0=tile*FTT;
        for (int i=tid;i<64*FTT;i+=512){
            int c=i>>7, t=i&(FTT-1), gt=t0+t;
            float v=(gt<TOUT)?g_skip[c*TOUT+gt]:0.0f;
            v=(v>0.f)?v:alpha[c]*v;
            sB0[addrB(c,t)]=pack_hl(v);
        }
        __syncthreads();

        float a0[4][4];
        #pragma unroll
        for (int b=0;b<4;b++){ a0[b][0]=a0[b][1]=a0[b][2]=a0[b][3]=0.f; }
        #pragma unroll
        for (int kc=0;kc<4;kc++){
            unsigned Ah[4],Al[4],Bh[4][2],Bl[4][2];
            loadA(sW0,wm,kc,4,lane,Ah,Al);
            #pragma unroll
            for (int nt=0;nt<4;nt++) loadB(sB0,kc,(n0>>3)+nt,lane,Bh[nt],Bl[nt]);
            #pragma unroll
            for (int nt=0;nt<4;nt++){
                mma_bf(a0[nt],Ah,Bh[nt]); mma_bf(a0[nt],Ah,Bl[nt]); mma_bf(a0[nt],Al,Bh[nt]);
            }
        }
        #pragma unroll
        for (int nt=0;nt<4;nt++){
            int tb=n0+nt*8+((lane&3)<<1);
            #pragma unroll
            for (int r=0;r<4;r++){
                int m=wm*16+(lane>>2)+((r&2)?8:0);
                float v=a0[nt][r]+b0p[m];
                v=(v>0.f)?v:alpha[64+m]*v;
                sB1[addrB(m,tb+(r&1))]=pack_hl(v);
            }
        }
        __syncthreads();

        float a1[4][4][4];
        #pragma unroll
        for (int a=0;a<4;a++)
            #pragma unroll
            for (int b=0;b<4;b++){ a1[a][b][0]=a1[a][b][1]=a1[a][b][2]=a1[a][b][3]=0.f; }
        #pragma unroll
        for (int kc=0;kc<4;kc++){
            unsigned Ah[4][4],Al[4][4],Bh[4][2],Bl[4][2];
            #pragma unroll
            for (int mt=0;mt<4;mt++) loadA(sW1,wm*4+mt,kc,4,lane,Ah[mt],Al[mt]);
            #pragma unroll
            for (int nt=0;nt<4;nt++) loadB(sB1,kc,(n0>>3)+nt,lane,Bh[nt],Bl[nt]);
            #pragma unroll
            for (int mt=0;mt<4;mt++)
                #pragma unroll
                for (int nt=0;nt<4;nt++){
                    mma_bf(a1[mt][nt],Ah[mt],Bh[nt]); mma_bf(a1[mt][nt],Ah[mt],Bl[nt]); mma_bf(a1[mt][nt],Al[mt],Bh[nt]);
                }
        }
        #pragma unroll
        for (int mt=0;mt<4;mt++){
            int mb=wm*64+mt*16+(lane>>2);
            #pragma unroll
            for (int nt=0;nt<4;nt++){
                int tb=n0+nt*8+((lane&3)<<1);
                #pragma unroll
                for (int r=0;r<4;r++){
                    int m=mb+((r&2)?8:0), gt=t0+tb+(r&1);
                    if (gt<TOUT) out[m*TOUT+gt]=a1[mt][nt][r]+b1p[m];
                }
            }
        }
        __syncthreads();
    }
}

extern "C" void kernel_launch(void* const* d_in, const int* in_sizes, int n_in,
                              void* d_out, int out_size) {
    const float* input =(const float*)d_in[0];
    const float* w0    =(const float*)d_in[1];
    const float* b0    =(const float*)d_in[2];
    const float* wf    =(const float*)d_in[3];
    const float* bf    =(const float*)d_in[4];
    const float* wg    =(const float*)d_in[5];
    const float* bg    =(const float*)d_in[6];
    const float* wr    =(const float*)d_in[7];
    const float* br    =(const float*)d_in[8];
    const float* ws    =(const float*)d_in[9];
    const float* bs    =(const float*)d_in[10];
    const float* alpha =(const float*)d_in[11];
    const float* w_out0=(const float*)d_in[12];
    const float* b_out0=(const float*)d_in[13];
    const float* w_out1=(const float*)d_in[14];
    const float* b_out1=(const float*)d_in[15];

    const int SMEM_FINAL = 36864*4;
    cudaFuncSetAttribute(layer_kernel, cudaFuncAttributeMaxDynamicSharedMemorySize, SM_LAYER);
    cudaFuncSetAttribute(final_kernel, cudaFuncAttributeMaxDynamicSharedMemorySize, SMEM_FINAL);

    init_kernel<<<512,256>>>(input, w0, b0, wf, wg, wr, ws);

    float* w1t_base = nullptr; float* w2t_base = nullptr;
    cudaGetSymbolAddress((void**)&w1t_base, g_w1t);
    cudaGetSymbolAddress((void**)&w2t_base, g_w2t);

    int W = HS, offset = 2048, buf = 0;
    for (int i = 0; i < NLAYER; i++){
        int d = 1 << (i % 10);
        offset -= d;
        layer_kernel<<<148,1024,SM_LAYER>>>(
            wf + i*64*64*2, wg + i*64*64*2, wr + i*64*64, ws + i*64*64,
            bf + i*64, bg + i*64, br + i*64, bs + i*64,
            w1t_base + i*128*128, w2t_base + i*64*128,
            buf, W, d, offset - 1);
        W -= d; buf ^= 1;
    }
    final_kernel<<<148,512,SMEM_FINAL>>>(alpha, w_out0, b_out0, w_out1, b_out1, (float*)d_out);
}

// round 16
// speedup vs baseline: 2.9112x; 2.6949x over previous
#include <cuda_runtime.h>
#include <cuda_bf16.h>
#include <cuda_fp16.h>
#include <math.h>

#define HS 65536
#define TOUT 63489
#define NLAYER 20
#define FTT 128

__device__ __half g_hh[2*64*HS + 8192];   // fp16 hi plane of h
__device__ __half g_hl[2*64*HS + 8192];   // fp16 lo plane
__device__ float g_skip[64*TOUT];

// ---- fp16 helpers (layer) ----
__device__ __forceinline__ unsigned pk2h(__half a, __half b){
    return (unsigned)__half_as_ushort(a) | ((unsigned)__half_as_ushort(b)<<16);
}
__device__ __forceinline__ void split2h(float a, float b, unsigned& h, unsigned& l){
    __half ha=__float2half_rn(a), hb=__float2half_rn(b);
    h = pk2h(ha,hb);
    l = pk2h(__float2half_rn(a-__half2float(ha)), __float2half_rn(b-__half2float(hb)));
}
__device__ __forceinline__ float hlo(unsigned u){ return __half2float(__ushort_as_half((unsigned short)(u&0xffff))); }
__device__ __forceinline__ float hhi(unsigned u){ return __half2float(__ushort_as_half((unsigned short)(u>>16))); }
__device__ __forceinline__ void ldsm4t(unsigned a, unsigned* d){
    asm volatile("ldmatrix.sync.aligned.m8n8.x4.trans.shared.b16 {%0,%1,%2,%3},[%4];"
        :"=r"(d[0]),"=r"(d[1]),"=r"(d[2]),"=r"(d[3]):"r"(a));
}
__device__ __forceinline__ void mma_h(float* d, const unsigned* a, const unsigned* b){
    asm volatile("mma.sync.aligned.m16n8k16.row.col.f32.f16.f16.f32 "
        "{%0,%1,%2,%3},{%4,%5,%6,%7},{%8,%9},{%0,%1,%2,%3};\n"
        :"+f"(d[0]),"+f"(d[1]),"+f"(d[2]),"+f"(d[3])
        :"r"(a[0]),"r"(a[1]),"r"(a[2]),"r"(a[3]),"r"(b[0]),"r"(b[1]));
}
// ---- bf16 helpers (head, unchanged R12 machinery) ----
__device__ __forceinline__ void mma_bf(float* d, const unsigned* a, const unsigned* b){
    asm volatile("mma.sync.aligned.m16n8k16.row.col.f32.bf16.bf16.f32 "
        "{%0,%1,%2,%3},{%4,%5,%6,%7},{%8,%9},{%0,%1,%2,%3};\n"
        :"+f"(d[0]),"+f"(d[1]),"+f"(d[2]),"+f"(d[3])
        :"r"(a[0]),"r"(a[1]),"r"(a[2]),"r"(a[3]),"r"(b[0]),"r"(b[1]));
}
// ---- MUFU-free activations (validated R12) ----
__device__ __forceinline__ float exp2_fma(float y){
    float ft = y + 12582912.0f;
    int ii = __float_as_int(ft) - 0x4B400000;
    float f = y - (ft - 12582912.0f);
    float p = 1.3333558146e-3f;
    p = fmaf(p, f, 9.6181291794e-3f);
    p = fmaf(p, f, 5.5504108664e-2f);
    p = fmaf(p, f, 2.4022650695e-1f);
    p = fmaf(p, f, 6.9314718056e-1f);
    p = fmaf(p, f, 1.0f);
    return p * __int_as_float((ii + 127) << 23);
}
__device__ __forceinline__ float rcp_12(float d){
    float r = fmaf(-0.470588235f, d, 1.411764706f);
    r = r * fmaf(-d, r, 2.0f);
    r = r * fmaf(-d, r, 2.0f);
    return r;
}
__device__ __forceinline__ float fast_tanh(float x){
    float u = exp2_fma(fmaxf(fabsf(x) * -2.88539008f, -30.0f));
    return copysignf((1.0f - u) * rcp_12(1.0f + u), x);
}
__device__ __forceinline__ float fast_sig(float x){
    float u = exp2_fma(fmaxf(fabsf(x) * -1.44269504f, -30.0f));
    float r = rcp_12(1.0f + u);
    return (x >= 0.0f) ? r : u * r;
}

__global__ void init_kernel(const float* __restrict__ in, const float* __restrict__ w0,
                            const float* __restrict__ b0){
    int st = gridDim.x*blockDim.x;
    for (int i = blockIdx.x*blockDim.x+threadIdx.x; i < 64*HS; i += st){
        float v = w0[i>>16]*in[i&(HS-1)] + b0[i>>16];
        __half h = __float2half_rn(v);
        g_hh[i] = h; g_hl[i] = __float2half_rn(v-__half2float(h));
    }
    for (int i = blockIdx.x*blockDim.x+threadIdx.x; i < 64*TOUT; i += st) g_skip[i] = 0.0f;
}

// smem bytes: Xhi[0,64K) Xlo[64K,128K) W1[128K,160K) W2[160K,176K)
#define SMEM_LAYER 180224
__global__ void __launch_bounds__(512,1) layer_kernel(
    const float* __restrict__ wf, const float* __restrict__ wg,
    const float* __restrict__ wr, const float* __restrict__ ws,
    const float* __restrict__ bfp, const float* __restrict__ bgp,
    const float* __restrict__ brp, const float* __restrict__ bsp,
    int inbuf, int W, int d, int skip_shift)
{
    extern __shared__ unsigned char smem[];
    unsigned char* sXh = smem;
    unsigned char* sXl = smem + 65536;
    unsigned* sW1 = (unsigned*)(smem+131072);
    unsigned* sW2 = (unsigned*)(smem+163840);
    const int tid=threadIdx.x, lane=tid&31, warp=tid>>5;
    const int tw = warp*16, tw3 = warp*2;

    const __half* hinh = g_hh + (size_t)inbuf*(64*HS);
    const __half* hinl = g_hl + (size_t)inbuf*(64*HS);
    __half* houth = g_hh + (size_t)(1-inbuf)*(64*HS);
    __half* houtl = g_hl + (size_t)(1-inbuf)*(64*HS);

    // stage weights (fp16, pair-packed) in mma A-fragment order
    for (int idx=tid; idx<128*64; idx+=512){
        int m=idx&127, k0=(idx>>7)*2;
        int c0=k0&63, l0=k0>>6, c1=(k0+1)&63, l1=(k0+1)>>6;
        float v0 = (m<64)? wf[(m*64+c0)*2+l0] : wg[((m-64)*64+c0)*2+l0];
        float v1 = (m<64)? wf[(m*64+c1)*2+l1] : wg[((m-64)*64+c1)*2+l1];
        int ml=m&15, kl=k0&15;
        int r = ((ml>>3)&1) | (((kl>>3)&1)<<1);
        int w = (((m>>4)*8 + (k0>>4))<<7) + ((ml&7)*4 + ((kl>>1)&3))*4 + r;
        sW1[w] = pk2h(__float2half_rn(v0), __float2half_rn(v1));
    }
    for (int idx=tid; idx<128*32; idx+=512){
        int m=idx&127, k0=(idx>>7)*2;
        float v0 = (m<64)? wr[m*64+k0]   : ws[(m-64)*64+k0];
        float v1 = (m<64)? wr[m*64+k0+1] : ws[(m-64)*64+k0+1];
        int ml=m&15, kl=k0&15;
        int r = ((ml>>3)&1) | (((kl>>3)&1)<<1);
        int w = (((m>>4)*4 + (k0>>4))<<7) + ((ml&7)*4 + ((kl>>1)&3))*4 + r;
        sW2[w] = pk2h(__float2half_rn(v0), __float2half_rn(v1));
    }
    __syncthreads();

    const int mat=lane>>3, r8=lane&7;
    const int koff=(mat&1)*8 + r8;
    const unsigned bofs = (unsigned)(koff*512 + (((tw3+(mat>>1))^r8)<<4));
    const unsigned xh_s = (unsigned)__cvta_generic_to_shared(sXh);
    const unsigned xl_s = (unsigned)__cvta_generic_to_shared(sXl);

    const int Wout = W-d;
    const int ntiles = (Wout+255)>>8;
    const int sh=d&7, q=sh>>1, odd=sh&1;

    for (int tile=blockIdx.x; tile<ntiles; tile+=gridDim.x){
        const int t0 = tile<<8;
        __syncwarp();
        #pragma unroll
        for (int it=0; it<2; it++){
            int c = lane + 32*it;
            size_t g = (size_t)c*HS + t0 + tw;
            int a0 = c*512 + (((tw3)^(c&7))<<4), a1 = c*512 + (((tw3+1)^(c&7))<<4);
            *(uint4*)(sXh+a0) = *(const uint4*)(hinh+g);
            *(uint4*)(sXh+a1) = *(const uint4*)(hinh+g+8);
            *(uint4*)(sXl+a0) = *(const uint4*)(hinl+g);
            *(uint4*)(sXl+a1) = *(const uint4*)(hinl+g+8);
            int k = 64+c;
            int b0a = k*512 + (((tw3)^(c&7))<<4), b1a = k*512 + (((tw3+1)^(c&7))<<4);
            if (sh==0){
                size_t gr = g + d;
                *(uint4*)(sXh+b0a) = *(const uint4*)(hinh+gr);
                *(uint4*)(sXh+b1a) = *(const uint4*)(hinh+gr+8);
                *(uint4*)(sXl+b0a) = *(const uint4*)(hinl+gr);
                *(uint4*)(sXl+b1a) = *(const uint4*)(hinl+gr+8);
            } else {
                size_t gr = g + (d - sh);
                unsigned wh[12], wl[12], oh[8], ol[8];
                *(uint4*)&wh[0]=*(const uint4*)(hinh+gr);   *(uint4*)&wh[4]=*(const uint4*)(hinh+gr+8);
                *(uint4*)&wh[8]=*(const uint4*)(hinh+gr+16);
                *(uint4*)&wl[0]=*(const uint4*)(hinl+gr);   *(uint4*)&wl[4]=*(const uint4*)(hinl+gr+8);
                *(uint4*)&wl[8]=*(const uint4*)(hinl+gr+16);
                #pragma unroll
                for (int i=0;i<8;i++){
                    int s=i+q;
                    oh[i] = odd ? __byte_perm(wh[s],wh[s+1],0x5432) : wh[s];
                    ol[i] = odd ? __byte_perm(wl[s],wl[s+1],0x5432) : wl[s];
                }
                *(uint4*)(sXh+b0a)=*(uint4*)&oh[0]; *(uint4*)(sXh+b1a)=*(uint4*)&oh[4];
                *(uint4*)(sXl+b0a)=*(uint4*)&ol[0]; *(uint4*)(sXl+b1a)=*(uint4*)&ol[4];
            }
        }
        __syncwarp();

        // GEMM1: M=128 N=16 K=128, 2 passes (X hi + X lo, weights fp16)
        float acc[8][2][4];
        #pragma unroll
        for (int a=0;a<8;a++)
            #pragma unroll
            for (int b=0;b<2;b++){ acc[a][b][0]=acc[a][b][1]=acc[a][b][2]=acc[a][b][3]=0.f; }
        #pragma unroll
        for (int kc=0;kc<8;kc++){
            unsigned bh[4], bl[4];
            ldsm4t(xh_s + bofs + kc*8192, bh);
            ldsm4t(xl_s + bofs + kc*8192, bl);
            #pragma unroll
            for (int mt=0;mt<8;mt++){
                uint4 A = *(const uint4*)(sW1 + ((mt*8+kc)<<7) + (lane<<2));
                unsigned a[4]={A.x,A.y,A.z,A.w};
                mma_h(acc[mt][0],a,bh);   mma_h(acc[mt][1],a,bh+2);
                mma_h(acc[mt][0],a,bl);   mma_h(acc[mt][1],a,bl+2);
            }
        }
        // activations + z -> rows 0..63 of X planes
        #pragma unroll
        for (int mt=0;mt<4;mt++)
            #pragma unroll
            for (int rp=0;rp<2;rp++){
                int mr = mt*16 + (lane>>2) + rp*8;
                float bfv=bfp[mr], bgv=bgp[mr];
                #pragma unroll
                for (int nt=0;nt<2;nt++){
                    float z0 = fast_tanh(acc[mt][nt][rp*2+0]+bfv)*fast_sig(acc[mt+4][nt][rp*2+0]+bgv);
                    float z1 = fast_tanh(acc[mt][nt][rp*2+1]+bfv)*fast_sig(acc[mt+4][nt][rp*2+1]+bgv);
                    unsigned zh,zl; split2h(z0,z1,zh,zl);
                    int ad = mr*512 + (((tw3+nt)^(mr&7))<<4) + ((lane&3)<<2);
                    *(unsigned*)(sXh+ad)=zh; *(unsigned*)(sXl+ad)=zl;
                }
            }
        __syncwarp();

        // GEMM2: M=128 N=16 K=64, 2 passes
        float ac2[8][2][4];
        #pragma unroll
        for (int a=0;a<8;a++)
            #pragma unroll
            for (int b=0;b<2;b++){ ac2[a][b][0]=ac2[a][b][1]=ac2[a][b][2]=ac2[a][b][3]=0.f; }
        #pragma unroll
        for (int kc=0;kc<4;kc++){
            unsigned bh[4], bl[4];
            ldsm4t(xh_s + bofs + kc*8192, bh);
            ldsm4t(xl_s + bofs + kc*8192, bl);
            #pragma unroll
            for (int mt=0;mt<8;mt++){
                uint4 A = *(const uint4*)(sW2 + ((mt*4+kc)<<7) + (lane<<2));
                unsigned a[4]={A.x,A.y,A.z,A.w};
                mma_h(ac2[mt][0],a,bh);   mma_h(ac2[mt][1],a,bh+2);
                mma_h(ac2[mt][0],a,bl);   mma_h(ac2[mt][1],a,bl+2);
            }
        }

        const bool full = (t0+256 <= Wout);
        #pragma unroll
        for (int mt=0;mt<4;mt++)
            #pragma unroll
            for (int rp=0;rp<2;rp++){
                int mr = mt*16 + (lane>>2) + rp*8;
                float bias = brp[mr];
                #pragma unroll
                for (int nt=0;nt<2;nt++){
                    int gt = t0 + tw + nt*8 + ((lane&3)<<1);
                    int ra = (64+mr)*512 + (((tw3+nt)^(mr&7))<<4) + ((lane&3)<<2);
                    unsigned rh=*(unsigned*)(sXh+ra), rl=*(unsigned*)(sXl+ra);
                    float v0 = ac2[mt][nt][rp*2+0] + bias + hlo(rh) + hlo(rl);
                    float v1 = ac2[mt][nt][rp*2+1] + bias + hhi(rh) + hhi(rl);
                    size_t go = (size_t)mr*HS + gt;
                    if (full){
                        unsigned oh,ol; split2h(v0,v1,oh,ol);
                        *(unsigned*)(houth+go)=oh; *(unsigned*)(houtl+go)=ol;
                    } else {
                        if (gt < Wout){ __half h=__float2half_rn(v0);
                            houth[go]=h; houtl[go]=__float2half_rn(v0-__half2float(h)); }
                        if (gt+1 < Wout){ __half h=__float2half_rn(v1);
                            houth[go+1]=h; houtl[go+1]=__float2half_rn(v1-__half2float(h)); }
                    }
                }
            }
        #pragma unroll
        for (int mt=4;mt<8;mt++)
            #pragma unroll
            for (int rp=0;rp<2;rp++){
                int sr = (mt-4)*16 + (lane>>2) + rp*8;
                float bias = bsp[sr];
                #pragma unroll
                for (int nt=0;nt<2;nt++){
                    int gt = t0 + tw + nt*8 + ((lane&3)<<1);
                    #pragma unroll
                    for (int e=0;e<2;e++){
                        int gc = gt+e - skip_shift;
                        if (gt+e < Wout && gc >= 0 && gc < TOUT){
                            float* p = &g_skip[sr*TOUT+gc];
                            *p = *p + ac2[mt][nt][rp*2+e] + bias;
                        }
                    }
                }
            }
    }
}

// -------- output head (R12 verbatim: bf16x3, reads g_skip only) --------
__device__ __forceinline__ unsigned pack_hl(float x){
    __nv_bfloat16 h=__float2bfloat16(x);
    __nv_bfloat16 l=__float2bfloat16(x-__bfloat162float(h));
    return (unsigned)__bfloat16_as_ushort(h) | ((unsigned)__bfloat16_as_ushort(l)<<16);
}
__device__ __forceinline__ int addrA(int m,int k,int kt){
    int ln=((m&7)<<2)|((k>>1)&3);
    int w=(k&1)|(((m>>3)&1)<<1)|(((k>>3)&1)<<2);
    return ((((m>>4)*kt+(k>>4))<<8)+(ln<<3)+w);
}
__device__ __forceinline__ int addrB(int k,int t){
    int ln=((t&7)<<2)|((k>>1)&3);
    int w=(k&1)|(((k>>3)&1)<<1);
    return ((((k>>4)*(FTT>>3)+(t>>3))<<7)+(ln<<2)+w);
}
__device__ __forceinline__ void loadA(const unsigned* s,int mt,int kc,int kt,int lane,unsigned* Ah,unsigned* Al){
    const uint4* p=(const uint4*)(s+(((mt*kt+kc)<<8)+(lane<<3)));
    uint4 q0=p[0],q1=p[1];
    Ah[0]=__byte_perm(q0.x,q0.y,0x5410); Al[0]=__byte_perm(q0.x,q0.y,0x7632);
    Ah[1]=__byte_perm(q0.z,q0.w,0x5410); Al[1]=__byte_perm(q0.z,q0.w,0x7632);
    Ah[2]=__byte_perm(q1.x,q1.y,0x5410); Al[2]=__byte_perm(q1.x,q1.y,0x7632);
    Ah[3]=__byte_perm(q1.z,q1.w,0x5410); Al[3]=__byte_perm(q1.z,q1.w,0x7632);
}
__device__ __forceinline__ void loadB(const unsigned* s,int kc,int nt,int lane,unsigned* Bh,unsigned* Bl){
    uint4 q=*(const uint4*)(s+(((kc*(FTT>>3)+nt)<<7)+(lane<<2)));
    Bh[0]=__byte_perm(q.x,q.y,0x5410); Bl[0]=__byte_perm(q.x,q.y,0x7632);
    Bh[1]=__byte_perm(q.z,q.w,0x5410); Bl[1]=__byte_perm(q.z,q.w,0x7632);
}
__global__ void __launch_bounds__(512,1) final_kernel(
    const float* __restrict__ alpha,
    const float* __restrict__ w0p, const float* __restrict__ b0p,
    const float* __restrict__ w1p, const float* __restrict__ b1p,
    float* __restrict__ out)
{
    extern __shared__ unsigned fs[];
    unsigned* sW0=fs; unsigned* sW1=fs+4096; unsigned* sB0=fs+20480; unsigned* sB1=fs+28672;
    const int tid=threadIdx.x, lane=tid&31, wrp=tid>>5;
    const int wm=wrp>>2, n0=(wrp&3)*32;

    for (int i=tid;i<64*64;i+=512) sW0[addrA(i>>6,i&63,4)]=pack_hl(w0p[i]);
    for (int i=tid;i<256*64;i+=512) sW1[addrA(i>>6,i&63,4)]=pack_hl(w1p[i]);
    __syncthreads();

    const int nt_total=(TOUT+FTT-1)/FTT;
    for (int tile=blockIdx.x; tile<nt_total; tile+=gridDim.x){
        const int t0=tile*FTT;
        for (int i=tid;i<64*FTT;i+=512){
            int c=i>>7, t=i&(FTT-1), gt=t0+t;
            float v=(gt<TOUT)?g_skip[c*TOUT+gt]:0.0f;
            v=(v>0.f)?v:alpha[c]*v;
            sB0[addrB(c,t)]=pack_hl(v);
        }
        __syncthreads();

        float a0[4][4];
        #pragma unroll
        for (int b=0;b<4;b++){ a0[b][0]=a0[b][1]=a0[b][2]=a0[b][3]=0.f; }
        #pragma unroll
        for (int kc=0;kc<4;kc++){
            unsigned Ah[4],Al[4],Bh[4][2],Bl[4][2];
            loadA(sW0,wm,kc,4,lane,Ah,Al);
            #pragma unroll
            for (int nt=0;nt<4;nt++) loadB(sB0,kc,(n0>>3)+nt,lane,Bh[nt],Bl[nt]);
            #pragma unroll
            for (int nt=0;nt<4;nt++){
                mma_bf(a0[nt],Ah,Bh[nt]); mma_bf(a0[nt],Ah,Bl[nt]); mma_bf(a0[nt],Al,Bh[nt]);
            }
        }
        #pragma unroll
        for (int nt=0;nt<4;nt++){
            int tb=n0+nt*8+((lane&3)<<1);
            #pragma unroll
            for (int r=0;r<4;r++){
                int m=wm*16+(lane>>2)+((r&2)?8:0);
                float v=a0[nt][r]+b0p[m];
                v=(v>0.f)?v:alpha[64+m]*v;
                sB1[addrB(m,tb+(r&1))]=pack_hl(v);
            }
        }
        __syncthreads();

        float a1[4][4][4];
        #pragma unroll
        for (int a=0;a<4;a++)
            #pragma unroll
            for (int b=0;b<4;b++){ a1[a][b][0]=a1[a][b][1]=a1[a][b][2]=a1[a][b][3]=0.f; }
        #pragma unroll
        for (int kc=0;kc<4;kc++){
            unsigned Ah[4][4],Al[4][4],Bh[4][2],Bl[4][2];
            #pragma unroll
            for (int mt=0;mt<4;mt++) loadA(sW1,wm*4+mt,kc,4,lane,Ah[mt],Al[mt]);
            #pragma unroll
            for (int nt=0;nt<4;nt++) loadB(sB1,kc,(n0>>3)+nt,lane,Bh[nt],Bl[nt]);
            #pragma unroll
            for (int mt=0;mt<4;mt++)
                #pragma unroll
                for (int nt=0;nt<4;nt++){
                    mma_bf(a1[mt][nt],Ah[mt],Bh[nt]); mma_bf(a1[mt][nt],Ah[mt],Bl[nt]); mma_bf(a1[mt][nt],Al[mt],Bh[nt]);
                }
        }
        #pragma unroll
        for (int mt=0;mt<4;mt++){
            int mb=wm*64+mt*16+(lane>>2);
            #pragma unroll
            for (int nt=0;nt<4;nt++){
                int tb=n0+nt*8+((lane&3)<<1);
                #pragma unroll
                for (int r=0;r<4;r++){
                    int m=mb+((r&2)?8:0), gt=t0+tb+(r&1);
                    if (gt<TOUT) out[m*TOUT+gt]=a1[mt][nt][r]+b1p[m];
                }
            }
        }
        __syncthreads();
    }
}

extern "C" void kernel_launch(void* const* d_in, const int* in_sizes, int n_in,
                              void* d_out, int out_size) {
    const float* input =(const float*)d_in[0];
    const float* w0    =(const float*)d_in[1];
    const float* b0    =(const float*)d_in[2];
    const float* wf    =(const float*)d_in[3];
    const float* bf    =(const float*)d_in[4];
    const float* wg    =(const float*)d_in[5];
    const float* bg    =(const float*)d_in[6];
    const float* wr    =(const float*)d_in[7];
    const float* br    =(const float*)d_in[8];
    const float* ws    =(const float*)d_in[9];
    const float* bs    =(const float*)d_in[10];
    const float* alpha =(const float*)d_in[11];
    const float* w_out0=(const float*)d_in[12];
    const float* b_out0=(const float*)d_in[13];
    const float* w_out1=(const float*)d_in[14];
    const float* b_out1=(const float*)d_in[15];

    const int SMEM_FINAL = 36864*4;
    cudaFuncSetAttribute(layer_kernel, cudaFuncAttributeMaxDynamicSharedMemorySize, SMEM_LAYER);
    cudaFuncSetAttribute(final_kernel, cudaFuncAttributeMaxDynamicSharedMemorySize, SMEM_FINAL);

    init_kernel<<<512,256>>>(input, w0, b0);

    int W = HS, offset = 2048, buf = 0;
    for (int i = 0; i < NLAYER; i++){
        int d = 1 << (i % 10);
        offset -= d;
        layer_kernel<<<148,512,SMEM_LAYER>>>(
            wf + i*64*64*2, wg + i*64*64*2, wr + i*64*64, ws + i*64*64,
            bf + i*64, bg + i*64, br + i*64, bs + i*64,
            buf, W, d, offset - 1);
        W -= d; buf ^= 1;
    }
    final_kernel<<<148,512,SMEM_FINAL>>>(alpha, w_out0, b_out0, w_out1, b_out1, (float*)d_out);
}